// round 1
// baseline (speedup 1.0000x reference)
#include <cuda_runtime.h>
#include <math.h>

#define S_LEN   4096
#define DMODEL  2048
#define NH      16
#define NKV     4
#define HD      128
#define KV_DIM  (NKV * HD)   // 512

// Scratch (allocation-free rule: __device__ globals)
__device__ float g_Q[S_LEN * DMODEL];   // 32 MB
__device__ float g_K[S_LEN * KV_DIM];   // 8 MB
__device__ float g_V[S_LEN * KV_DIM];   // 8 MB
__device__ float g_O[S_LEN * DMODEL];   // 32 MB

// ---------------------------------------------------------------------------
// Generic tiled SGEMM: C[M,N] = A[M,K] @ B[K,N], row-major, all dims %64==0,K%16==0
// 64x64 block tile, BK=16, 256 threads, 4x4 per-thread microtile.
// ---------------------------------------------------------------------------
__global__ __launch_bounds__(256) void sgemm64(const float* __restrict__ A,
                                               const float* __restrict__ B,
                                               float* __restrict__ C,
                                               int M, int N, int K)
{
    __shared__ float sA[16 * 68];   // [k][row] transposed, padded
    __shared__ float sB[16 * 68];   // [k][col] padded

    const int tid = threadIdx.x;
    const int tx = tid & 15;        // col group
    const int ty = tid >> 4;        // row group
    const int n0 = blockIdx.x * 64;
    const int m0 = blockIdx.y * 64;

    const int arow = tid >> 2;            // 0..63
    const int acol = (tid & 3) << 2;      // 0,4,8,12
    const int brow = tid >> 4;            // 0..15
    const int bcol = (tid & 15) << 2;     // 0..60

    float acc[4][4] = {};

    for (int kk = 0; kk < K; kk += 16) {
        __syncthreads();
        float4 a = *(const float4*)&A[(size_t)(m0 + arow) * K + kk + acol];
        sA[(acol + 0) * 68 + arow] = a.x;
        sA[(acol + 1) * 68 + arow] = a.y;
        sA[(acol + 2) * 68 + arow] = a.z;
        sA[(acol + 3) * 68 + arow] = a.w;
        *(float4*)&sB[brow * 68 + bcol] =
            *(const float4*)&B[(size_t)(kk + brow) * N + n0 + bcol];
        __syncthreads();

        #pragma unroll
        for (int k = 0; k < 16; k++) {
            float4 av = *(const float4*)&sA[k * 68 + 4 * ty];
            float4 bv = *(const float4*)&sB[k * 68 + 4 * tx];
            float aa[4] = {av.x, av.y, av.z, av.w};
            float bb[4] = {bv.x, bv.y, bv.z, bv.w};
            #pragma unroll
            for (int i = 0; i < 4; i++)
                #pragma unroll
                for (int j = 0; j < 4; j++)
                    acc[i][j] += aa[i] * bb[j];
        }
    }

    #pragma unroll
    for (int i = 0; i < 4; i++) {
        *(float4*)&C[(size_t)(m0 + 4 * ty + i) * N + n0 + 4 * tx] =
            make_float4(acc[i][0], acc[i][1], acc[i][2], acc[i][3]);
    }
}

// ---------------------------------------------------------------------------
// RoPE applied in-place to g_Q (16 heads) and g_K (4 heads).
// out[d]    = x[d]   * cos[d]    - x[d+64] * sin[d]      (d < 64)
// out[d+64] = x[d+64]* cos[d+64] + x[d]    * sin[d+64]
// ---------------------------------------------------------------------------
__global__ void rope_kernel(const float* __restrict__ cosp,
                            const float* __restrict__ sinp)
{
    const int per_s = (NH + NKV) * 64;
    int idx = blockIdx.x * blockDim.x + threadIdx.x;
    if (idx >= S_LEN * per_s) return;
    int s  = idx / per_s;
    int r  = idx % per_s;
    int hh = r >> 6;
    int d  = r & 63;

    float* p;
    if (hh < NH) p = g_Q + (size_t)s * DMODEL + hh * HD;
    else         p = g_K + (size_t)s * KV_DIM + (hh - NH) * HD;

    float c0 = cosp[s * HD + d],      s0 = sinp[s * HD + d];
    float c1 = cosp[s * HD + d + 64], s1 = sinp[s * HD + d + 64];
    float x0 = p[d], x1 = p[d + 64];
    p[d]      = x0 * c0 - x1 * s0;
    p[d + 64] = x1 * c1 + x0 * s1;
}

// ---------------------------------------------------------------------------
// Flash attention, fp32, causal, online softmax.
// Block: 64 query rows of one head; 256 threads.
// Smem: Qt[128][68] (d-major), Kt[128][68] (d-major), Vs[64][132], Pt[64][68]
// Thread t: ty=t/16 (4 rows), tx=t%16 (4 S-cols / 8 O-cols).
// ---------------------------------------------------------------------------
__global__ __launch_bounds__(256) void flash_kernel()
{
    extern __shared__ float sm[];
    float* sQt = sm;                // 128*68 = 8704
    float* sKt = sm + 8704;         // 128*68
    float* sVs = sm + 17408;        // 64*132 = 8448
    float* sPt = sm + 25856;        // 64*68  = 4352   total 30208 f = 120832 B

    const int tid = threadIdx.x;
    const int tx = tid & 15;
    const int ty = tid >> 4;
    const int qb = gridDim.x - 1 - blockIdx.x;   // heavy blocks first
    const int h  = blockIdx.y;
    const int kvh = h >> 2;                      // GQA group of 4
    const int q0 = qb * 64;
    const float scale = 0.08838834764831845f;    // 1/sqrt(128)

    // Load Q tile (rows q0..q0+63, 128 d) transposed into sQt[d][row]
    for (int i = tid; i < 64 * 32; i += 256) {
        int row = i >> 5;
        int dq  = (i & 31) << 2;
        float4 v = *(const float4*)&g_Q[(size_t)(q0 + row) * DMODEL + h * HD + dq];
        sQt[(dq + 0) * 68 + row] = v.x;
        sQt[(dq + 1) * 68 + row] = v.y;
        sQt[(dq + 2) * 68 + row] = v.z;
        sQt[(dq + 3) * 68 + row] = v.w;
    }

    float m[4], l[4], o[4][8];
    #pragma unroll
    for (int i = 0; i < 4; i++) {
        m[i] = -1e30f; l[i] = 0.f;
        #pragma unroll
        for (int j = 0; j < 8; j++) o[i][j] = 0.f;
    }

    for (int kb = 0; kb <= qb; kb++) {
        const int k0 = kb * 64;
        // Load K (transposed) and V tiles
        for (int i = tid; i < 64 * 32; i += 256) {
            int key = i >> 5;
            int dq  = (i & 31) << 2;
            float4 kv = *(const float4*)&g_K[(size_t)(k0 + key) * KV_DIM + kvh * HD + dq];
            sKt[(dq + 0) * 68 + key] = kv.x;
            sKt[(dq + 1) * 68 + key] = kv.y;
            sKt[(dq + 2) * 68 + key] = kv.z;
            sKt[(dq + 3) * 68 + key] = kv.w;
            float4 vv = *(const float4*)&g_V[(size_t)(k0 + key) * KV_DIM + kvh * HD + dq];
            *(float4*)&sVs[key * 132 + dq] = vv;
        }
        __syncthreads();

        // S = Q @ K^T  (64x64 tile, 4x4 per thread)
        float acc[4][4] = {};
        #pragma unroll 8
        for (int d = 0; d < 128; d++) {
            float4 av = *(const float4*)&sQt[d * 68 + 4 * ty];
            float4 bv = *(const float4*)&sKt[d * 68 + 4 * tx];
            float aa[4] = {av.x, av.y, av.z, av.w};
            float bb[4] = {bv.x, bv.y, bv.z, bv.w};
            #pragma unroll
            for (int i = 0; i < 4; i++)
                #pragma unroll
                for (int j = 0; j < 4; j++)
                    acc[i][j] += aa[i] * bb[j];
        }

        const bool diag = (kb == qb);
        #pragma unroll
        for (int i = 0; i < 4; i++) {
            // scale + causal mask + row max (16 lanes share a row)
            float rmax = -1e30f;
            #pragma unroll
            for (int j = 0; j < 4; j++) {
                float v = acc[i][j] * scale;
                if (diag && (4 * tx + j) > (4 * ty + i)) v = -1e30f;
                acc[i][j] = v;
                rmax = fmaxf(rmax, v);
            }
            #pragma unroll
            for (int off = 8; off > 0; off >>= 1)
                rmax = fmaxf(rmax, __shfl_xor_sync(0xffffffffu, rmax, off));

            float mn = fmaxf(m[i], rmax);
            float alpha = __expf(m[i] - mn);
            float rs = 0.f;
            #pragma unroll
            for (int j = 0; j < 4; j++) {
                float p = __expf(acc[i][j] - mn);
                acc[i][j] = p;
                rs += p;
            }
            #pragma unroll
            for (int off = 8; off > 0; off >>= 1)
                rs += __shfl_xor_sync(0xffffffffu, rs, off);

            l[i] = l[i] * alpha + rs;
            m[i] = mn;
            #pragma unroll
            for (int j = 0; j < 8; j++) o[i][j] *= alpha;

            *(float4*)&sPt[(4 * ty + i) * 68 + 4 * tx] =
                make_float4(acc[i][0], acc[i][1], acc[i][2], acc[i][3]);
        }
        __syncthreads();

        // O += P @ V  (64x128 tile, 4x8 per thread)
        #pragma unroll 2
        for (int k = 0; k < 64; k++) {
            float a0 = sPt[(4 * ty + 0) * 68 + k];
            float a1 = sPt[(4 * ty + 1) * 68 + k];
            float a2 = sPt[(4 * ty + 2) * 68 + k];
            float a3 = sPt[(4 * ty + 3) * 68 + k];
            float4 b0 = *(const float4*)&sVs[k * 132 + 8 * tx];
            float4 b1 = *(const float4*)&sVs[k * 132 + 8 * tx + 4];
            float aa[4] = {a0, a1, a2, a3};
            float bb[8] = {b0.x, b0.y, b0.z, b0.w, b1.x, b1.y, b1.z, b1.w};
            #pragma unroll
            for (int i = 0; i < 4; i++)
                #pragma unroll
                for (int j = 0; j < 8; j++)
                    o[i][j] += aa[i] * bb[j];
        }
        __syncthreads();
    }

    // Normalize and store
    #pragma unroll
    for (int i = 0; i < 4; i++) {
        float inv = 1.0f / l[i];
        float* dst = &g_O[(size_t)(q0 + 4 * ty + i) * DMODEL + h * HD + 8 * tx];
        *(float4*)dst       = make_float4(o[i][0] * inv, o[i][1] * inv,
                                          o[i][2] * inv, o[i][3] * inv);
        *(float4*)(dst + 4) = make_float4(o[i][4] * inv, o[i][5] * inv,
                                          o[i][6] * inv, o[i][7] * inv);
    }
}

// ---------------------------------------------------------------------------
extern "C" void kernel_launch(void* const* d_in, const int* in_sizes, int n_in,
                              void* d_out, int out_size)
{
    const float* X    = (const float*)d_in[0];   // hidden_states [4096,2048]
    const float* cosp = (const float*)d_in[1];   // [4096,128]
    const float* sinp = (const float*)d_in[2];   // [4096,128]
    const float* Wq   = (const float*)d_in[3];   // [2048,2048]
    const float* Wk   = (const float*)d_in[4];   // [2048,512]
    const float* Wv   = (const float*)d_in[5];   // [2048,512]
    const float* Wo   = (const float*)d_in[6];   // [2048,2048]
    float* out = (float*)d_out;

    float *gQ, *gK, *gV, *gO;
    cudaGetSymbolAddress((void**)&gQ, g_Q);
    cudaGetSymbolAddress((void**)&gK, g_K);
    cudaGetSymbolAddress((void**)&gV, g_V);
    cudaGetSymbolAddress((void**)&gO, g_O);

    // QKV projections
    sgemm64<<<dim3(DMODEL / 64, S_LEN / 64), 256>>>(X, Wq, gQ, S_LEN, DMODEL, DMODEL);
    sgemm64<<<dim3(KV_DIM / 64, S_LEN / 64), 256>>>(X, Wk, gK, S_LEN, KV_DIM, DMODEL);
    sgemm64<<<dim3(KV_DIM / 64, S_LEN / 64), 256>>>(X, Wv, gV, S_LEN, KV_DIM, DMODEL);

    // RoPE on Q and K
    int rthreads = S_LEN * (NH + NKV) * 64;
    rope_kernel<<<(rthreads + 255) / 256, 256>>>(cosp, sinp);

    // Flash attention
    cudaFuncSetAttribute(flash_kernel, cudaFuncAttributeMaxDynamicSharedMemorySize,
                         120832);
    flash_kernel<<<dim3(S_LEN / 64, NH), 256, 120832>>>();

    // Output projection
    sgemm64<<<dim3(DMODEL / 64, S_LEN / 64), 256>>>(gO, Wo, out, S_LEN, DMODEL, DMODEL);
}

// round 3
// speedup vs baseline: 1.3172x; 1.3172x over previous
#include <cuda_runtime.h>
#include <cuda_bf16.h>
#include <cstdint>
#include <math.h>

#define S_LEN   4096
#define DMODEL  2048
#define NH      16
#define NKV     4
#define HD      128
#define KV_DIM  (NKV * HD)   // 512

// ---------------- device scratch (allocation-free rule) ----------------
__device__ float g_Q[S_LEN * DMODEL];
__device__ float g_K[S_LEN * KV_DIM];
__device__ float g_V[S_LEN * KV_DIM];
__device__ float g_O[S_LEN * DMODEL];

__device__ __nv_bfloat16 g_Xhi[S_LEN * DMODEL];
__device__ __nv_bfloat16 g_Xlo[S_LEN * DMODEL];
__device__ __nv_bfloat16 g_Ohi[S_LEN * DMODEL];
__device__ __nv_bfloat16 g_Olo[S_LEN * DMODEL];
__device__ __nv_bfloat16 g_WqThi[DMODEL * DMODEL];
__device__ __nv_bfloat16 g_WqTlo[DMODEL * DMODEL];
__device__ __nv_bfloat16 g_WkThi[KV_DIM * DMODEL];
__device__ __nv_bfloat16 g_WkTlo[KV_DIM * DMODEL];
__device__ __nv_bfloat16 g_WvThi[KV_DIM * DMODEL];
__device__ __nv_bfloat16 g_WvTlo[KV_DIM * DMODEL];
__device__ __nv_bfloat16 g_WoThi[DMODEL * DMODEL];
__device__ __nv_bfloat16 g_WoTlo[DMODEL * DMODEL];

// ---------------- PTX helpers (compute_103-safe: sm_80-era ISA) ----------------
__device__ __forceinline__ uint32_t smem_u32(const void* p) {
    uint32_t a;
    asm("{ .reg .u64 t; cvta.to.shared.u64 t, %1; cvt.u32.u64 %0, t; }"
        : "=r"(a) : "l"(p));
    return a;
}
__device__ __forceinline__ void cp_async16(uint32_t dst, const void* src) {
    asm volatile("cp.async.cg.shared.global [%0], [%1], 16;" :: "r"(dst), "l"(src));
}
#define CP_COMMIT() asm volatile("cp.async.commit_group;" ::: "memory")
#define CP_WAIT(n)  asm volatile("cp.async.wait_group %0;" :: "n"(n) : "memory")

__device__ __forceinline__ void ldm_x4(uint32_t& r0, uint32_t& r1, uint32_t& r2,
                                       uint32_t& r3, uint32_t addr) {
    asm volatile("ldmatrix.sync.aligned.m8n8.x4.shared.b16 {%0,%1,%2,%3}, [%4];"
                 : "=r"(r0), "=r"(r1), "=r"(r2), "=r"(r3) : "r"(addr));
}
__device__ __forceinline__ void mma_bf16(float& d0, float& d1, float& d2, float& d3,
                                         uint32_t a0, uint32_t a1, uint32_t a2,
                                         uint32_t a3, uint32_t b0, uint32_t b1) {
    asm volatile(
        "mma.sync.aligned.m16n8k16.row.col.f32.bf16.bf16.f32 "
        "{%0,%1,%2,%3}, {%4,%5,%6,%7}, {%8,%9}, {%0,%1,%2,%3};"
        : "+f"(d0), "+f"(d1), "+f"(d2), "+f"(d3)
        : "r"(a0), "r"(a1), "r"(a2), "r"(a3), "r"(b0), "r"(b1));
}

// ---------------------------------------------------------------------------
// Split fp32 -> (bf16 hi, bf16 lo)
// ---------------------------------------------------------------------------
__global__ void split_rm(const float* __restrict__ src,
                         __nv_bfloat16* __restrict__ hi,
                         __nv_bfloat16* __restrict__ lo, int n)
{
    int i = blockIdx.x * blockDim.x + threadIdx.x;
    if (i >= n) return;
    float f = src[i];
    __nv_bfloat16 h = __float2bfloat16(f);
    hi[i] = h;
    lo[i] = __float2bfloat16(f - __bfloat162float(h));
}

// ---------------------------------------------------------------------------
// Split + transpose: W[K,N] fp32 -> hiT/loT [N,K] bf16
// ---------------------------------------------------------------------------
__global__ __launch_bounds__(256) void split_tr(const float* __restrict__ W,
                                                __nv_bfloat16* __restrict__ hiT,
                                                __nv_bfloat16* __restrict__ loT,
                                                int K, int N)
{
    __shared__ float s[32][33];
    int n0 = blockIdx.x * 32, k0 = blockIdx.y * 32;
    int tx = threadIdx.x & 31, ty = threadIdx.x >> 5;
    #pragma unroll
    for (int j = 0; j < 4; j++)
        s[ty + j * 8][tx] = W[(size_t)(k0 + ty + j * 8) * N + n0 + tx];
    __syncthreads();
    #pragma unroll
    for (int j = 0; j < 4; j++) {
        int nn = ty + j * 8;
        float f = s[tx][nn];
        __nv_bfloat16 h = __float2bfloat16(f);
        size_t o = (size_t)(n0 + nn) * K + k0 + tx;
        hiT[o] = h;
        loT[o] = __float2bfloat16(f - __bfloat162float(h));
    }
}

// ---------------------------------------------------------------------------
// mma.sync bf16x3 GEMM: C[M,N] = (Ahi+Alo)[M,K] @ ((Bhi+Blo)[N,K])^T, fp32 out
// CTA 128x128, BK=32, 8 warps (warp tile 64x32), double-buffered cp.async.
// SMEM stage: 4 planes x 128 rows x 80B (32 bf16 + pad) = 40960B; x2 stages.
// ---------------------------------------------------------------------------
#define GS_TILE   10240          // 128 * 80
#define GS_STAGE  40960          // 4 tiles
#define GEMM_SMEM 81920          // 2 stages

__global__ __launch_bounds__(256, 2) void gemm_mma(
    const __nv_bfloat16* __restrict__ Ahi, const __nv_bfloat16* __restrict__ Alo,
    const __nv_bfloat16* __restrict__ Bhi, const __nv_bfloat16* __restrict__ Blo,
    float* __restrict__ C, int M, int N, int K)
{
    extern __shared__ char dsm[];
    const uint32_t sbase = smem_u32(dsm);

    const int tid  = threadIdx.x;
    const int lane = tid & 31;
    const int w    = tid >> 5;
    const int wm   = w >> 2;          // 0..1  (row half, 64 rows)
    const int wn   = w & 3;           // 0..3  (col quarter, 32 cols)
    const int n0 = blockIdx.x * 128, m0 = blockIdx.y * 128;

    const __nv_bfloat16* srcs[4] = {
        Ahi + (size_t)m0 * K, Alo + (size_t)m0 * K,
        Bhi + (size_t)n0 * K, Blo + (size_t)n0 * K };

    // --- stage loader: 4 tiles x 128 rows x 4 x 16B chunks = 2048 cp.async ---
    auto load_stage = [&](int stg, int kk) {
        uint32_t sb = sbase + stg * GS_STAGE;
        #pragma unroll
        for (int it = 0; it < 8; it++) {
            int idx  = it * 256 + tid;
            int tile = idx >> 9;
            int rem  = idx & 511;
            int r    = rem >> 2;
            int c    = rem & 3;
            cp_async16(sb + tile * GS_TILE + r * 80 + c * 16,
                       srcs[tile] + (size_t)r * K + kk + c * 8);
        }
        CP_COMMIT();
    };

    float acc[4][4][4];
    #pragma unroll
    for (int i = 0; i < 4; i++)
        #pragma unroll
        for (int j = 0; j < 4; j++)
            #pragma unroll
            for (int q = 0; q < 4; q++) acc[i][j][q] = 0.f;

    const int ns = K >> 5;
    load_stage(0, 0);

    for (int i = 0; i < ns; i++) {
        if (i + 1 < ns) { load_stage((i + 1) & 1, (i + 1) * 32); CP_WAIT(1); }
        else            { CP_WAIT(0); }
        __syncthreads();

        const uint32_t sb  = sbase + (i & 1) * GS_STAGE;
        const uint32_t ldr = (lane & 15);
        const uint32_t ldc = (lane >> 4) * 16;          // byte offset: 8 bf16

        #pragma unroll
        for (int ks = 0; ks < 2; ks++) {
            const uint32_t kboff = ks * 32 + ldc;       // bytes within 64B row payload
            // A fragments: 2 planes x 4 m-tiles
            uint32_t af[2][4][4];
            #pragma unroll
            for (int p = 0; p < 2; p++)
                #pragma unroll
                for (int mt = 0; mt < 4; mt++)
                    ldm_x4(af[p][mt][0], af[p][mt][1], af[p][mt][2], af[p][mt][3],
                           sb + p * GS_TILE +
                           (wm * 64 + mt * 16 + ldr) * 80 + kboff);

            #pragma unroll
            for (int nh = 0; nh < 2; nh++) {
                // B fragments for 16 n (2 n-tiles), both planes
                uint32_t bf[2][4];
                #pragma unroll
                for (int p = 0; p < 2; p++)
                    ldm_x4(bf[p][0], bf[p][1], bf[p][2], bf[p][3],
                           sb + (2 + p) * GS_TILE +
                           (wn * 32 + nh * 16 + ldr) * 80 + kboff);

                #pragma unroll
                for (int mt = 0; mt < 4; mt++) {
                    #pragma unroll
                    for (int sub = 0; sub < 2; sub++) {
                        const int nt = nh * 2 + sub;
                        float* d = acc[mt][nt];
                        // hi*hi
                        mma_bf16(d[0], d[1], d[2], d[3],
                                 af[0][mt][0], af[0][mt][1], af[0][mt][2], af[0][mt][3],
                                 bf[0][sub], bf[0][sub + 2]);
                        // hi*lo
                        mma_bf16(d[0], d[1], d[2], d[3],
                                 af[0][mt][0], af[0][mt][1], af[0][mt][2], af[0][mt][3],
                                 bf[1][sub], bf[1][sub + 2]);
                        // lo*hi
                        mma_bf16(d[0], d[1], d[2], d[3],
                                 af[1][mt][0], af[1][mt][1], af[1][mt][2], af[1][mt][3],
                                 bf[0][sub], bf[0][sub + 2]);
                    }
                }
            }
        }
        __syncthreads();
    }

    // --- epilogue: fp32 direct store ---
    const int trow = lane >> 2;
    const int tcol = (lane & 3) * 2;
    #pragma unroll
    for (int mt = 0; mt < 4; mt++) {
        #pragma unroll
        for (int nt = 0; nt < 4; nt++) {
            const int rr = m0 + wm * 64 + mt * 16 + trow;
            const int cc = n0 + wn * 32 + nt * 8 + tcol;
            *(float2*)&C[(size_t)rr * N + cc] =
                make_float2(acc[mt][nt][0], acc[mt][nt][1]);
            *(float2*)&C[(size_t)(rr + 8) * N + cc] =
                make_float2(acc[mt][nt][2], acc[mt][nt][3]);
        }
    }
}

// ---------------------------------------------------------------------------
// RoPE in-place on g_Q (16 heads) and g_K (4 heads)
// ---------------------------------------------------------------------------
__global__ void rope_kernel(const float* __restrict__ cosp,
                            const float* __restrict__ sinp)
{
    const int per_s = (NH + NKV) * 64;
    int idx = blockIdx.x * blockDim.x + threadIdx.x;
    if (idx >= S_LEN * per_s) return;
    int s = idx / per_s;
    int r = idx % per_s;
    int hh = r >> 6;
    int d = r & 63;

    float* p;
    if (hh < NH) p = g_Q + (size_t)s * DMODEL + hh * HD;
    else         p = g_K + (size_t)s * KV_DIM + (hh - NH) * HD;

    float c0 = cosp[s * HD + d],      s0 = sinp[s * HD + d];
    float c1 = cosp[s * HD + d + 64], s1 = sinp[s * HD + d + 64];
    float x0 = p[d], x1 = p[d + 64];
    p[d]      = x0 * c0 - x1 * s0;
    p[d + 64] = x1 * c1 + x0 * s1;
}

// ---------------------------------------------------------------------------
// Flash attention, fp32 SIMT, causal, online softmax (R1-verified)
// ---------------------------------------------------------------------------
__global__ __launch_bounds__(256) void flash_kernel()
{
    extern __shared__ float sm[];
    float* sQt = sm;
    float* sKt = sm + 8704;
    float* sVs = sm + 17408;
    float* sPt = sm + 25856;

    const int tid = threadIdx.x;
    const int tx = tid & 15;
    const int ty = tid >> 4;
    const int qb = gridDim.x - 1 - blockIdx.x;
    const int h  = blockIdx.y;
    const int kvh = h >> 2;
    const int q0 = qb * 64;
    const float scale = 0.08838834764831845f;

    for (int i = tid; i < 64 * 32; i += 256) {
        int row = i >> 5;
        int dq  = (i & 31) << 2;
        float4 v = *(const float4*)&g_Q[(size_t)(q0 + row) * DMODEL + h * HD + dq];
        sQt[(dq + 0) * 68 + row] = v.x;
        sQt[(dq + 1) * 68 + row] = v.y;
        sQt[(dq + 2) * 68 + row] = v.z;
        sQt[(dq + 3) * 68 + row] = v.w;
    }

    float m[4], l[4], o[4][8];
    #pragma unroll
    for (int i = 0; i < 4; i++) {
        m[i] = -1e30f; l[i] = 0.f;
        #pragma unroll
        for (int j = 0; j < 8; j++) o[i][j] = 0.f;
    }

    for (int kb = 0; kb <= qb; kb++) {
        const int k0 = kb * 64;
        for (int i = tid; i < 64 * 32; i += 256) {
            int key = i >> 5;
            int dq  = (i & 31) << 2;
            float4 kv = *(const float4*)&g_K[(size_t)(k0 + key) * KV_DIM + kvh * HD + dq];
            sKt[(dq + 0) * 68 + key] = kv.x;
            sKt[(dq + 1) * 68 + key] = kv.y;
            sKt[(dq + 2) * 68 + key] = kv.z;
            sKt[(dq + 3) * 68 + key] = kv.w;
            float4 vv = *(const float4*)&g_V[(size_t)(k0 + key) * KV_DIM + kvh * HD + dq];
            *(float4*)&sVs[key * 132 + dq] = vv;
        }
        __syncthreads();

        float acc[4][4] = {};
        #pragma unroll 8
        for (int d = 0; d < 128; d++) {
            float4 av = *(const float4*)&sQt[d * 68 + 4 * ty];
            float4 bv = *(const float4*)&sKt[d * 68 + 4 * tx];
            float aa[4] = {av.x, av.y, av.z, av.w};
            float bb[4] = {bv.x, bv.y, bv.z, bv.w};
            #pragma unroll
            for (int i = 0; i < 4; i++)
                #pragma unroll
                for (int j = 0; j < 4; j++)
                    acc[i][j] += aa[i] * bb[j];
        }

        const bool diag = (kb == qb);
        #pragma unroll
        for (int i = 0; i < 4; i++) {
            float rmax = -1e30f;
            #pragma unroll
            for (int j = 0; j < 4; j++) {
                float v = acc[i][j] * scale;
                if (diag && (4 * tx + j) > (4 * ty + i)) v = -1e30f;
                acc[i][j] = v;
                rmax = fmaxf(rmax, v);
            }
            #pragma unroll
            for (int off = 8; off > 0; off >>= 1)
                rmax = fmaxf(rmax, __shfl_xor_sync(0xffffffffu, rmax, off));

            float mn = fmaxf(m[i], rmax);
            float alpha = __expf(m[i] - mn);
            float rs = 0.f;
            #pragma unroll
            for (int j = 0; j < 4; j++) {
                float p = __expf(acc[i][j] - mn);
                acc[i][j] = p;
                rs += p;
            }
            #pragma unroll
            for (int off = 8; off > 0; off >>= 1)
                rs += __shfl_xor_sync(0xffffffffu, rs, off);

            l[i] = l[i] * alpha + rs;
            m[i] = mn;
            #pragma unroll
            for (int j = 0; j < 8; j++) o[i][j] *= alpha;

            *(float4*)&sPt[(4 * ty + i) * 68 + 4 * tx] =
                make_float4(acc[i][0], acc[i][1], acc[i][2], acc[i][3]);
        }
        __syncthreads();

        #pragma unroll 2
        for (int k = 0; k < 64; k++) {
            float a0 = sPt[(4 * ty + 0) * 68 + k];
            float a1 = sPt[(4 * ty + 1) * 68 + k];
            float a2 = sPt[(4 * ty + 2) * 68 + k];
            float a3 = sPt[(4 * ty + 3) * 68 + k];
            float4 b0 = *(const float4*)&sVs[k * 132 + 8 * tx];
            float4 b1 = *(const float4*)&sVs[k * 132 + 8 * tx + 4];
            float aa[4] = {a0, a1, a2, a3};
            float bb[8] = {b0.x, b0.y, b0.z, b0.w, b1.x, b1.y, b1.z, b1.w};
            #pragma unroll
            for (int i = 0; i < 4; i++)
                #pragma unroll
                for (int j = 0; j < 8; j++)
                    o[i][j] += aa[i] * bb[j];
        }
        __syncthreads();
    }

    #pragma unroll
    for (int i = 0; i < 4; i++) {
        float inv = 1.0f / l[i];
        float* dst = &g_O[(size_t)(q0 + 4 * ty + i) * DMODEL + h * HD + 8 * tx];
        *(float4*)dst       = make_float4(o[i][0] * inv, o[i][1] * inv,
                                          o[i][2] * inv, o[i][3] * inv);
        *(float4*)(dst + 4) = make_float4(o[i][4] * inv, o[i][5] * inv,
                                          o[i][6] * inv, o[i][7] * inv);
    }
}

// ---------------------------------------------------------------------------
extern "C" void kernel_launch(void* const* d_in, const int* in_sizes, int n_in,
                              void* d_out, int out_size)
{
    const float* X    = (const float*)d_in[0];
    const float* cosp = (const float*)d_in[1];
    const float* sinp = (const float*)d_in[2];
    const float* Wq   = (const float*)d_in[3];
    const float* Wk   = (const float*)d_in[4];
    const float* Wv   = (const float*)d_in[5];
    const float* Wo   = (const float*)d_in[6];
    float* out = (float*)d_out;

    float *gQ, *gK, *gV, *gO;
    cudaGetSymbolAddress((void**)&gQ, g_Q);
    cudaGetSymbolAddress((void**)&gK, g_K);
    cudaGetSymbolAddress((void**)&gV, g_V);
    cudaGetSymbolAddress((void**)&gO, g_O);
    __nv_bfloat16 *xh, *xl, *oh, *ol, *qh, *ql, *kh, *kl, *vh, *vl, *wh, *wl;
    cudaGetSymbolAddress((void**)&xh, g_Xhi);  cudaGetSymbolAddress((void**)&xl, g_Xlo);
    cudaGetSymbolAddress((void**)&oh, g_Ohi);  cudaGetSymbolAddress((void**)&ol, g_Olo);
    cudaGetSymbolAddress((void**)&qh, g_WqThi); cudaGetSymbolAddress((void**)&ql, g_WqTlo);
    cudaGetSymbolAddress((void**)&kh, g_WkThi); cudaGetSymbolAddress((void**)&kl, g_WkTlo);
    cudaGetSymbolAddress((void**)&vh, g_WvThi); cudaGetSymbolAddress((void**)&vl, g_WvTlo);
    cudaGetSymbolAddress((void**)&wh, g_WoThi); cudaGetSymbolAddress((void**)&wl, g_WoTlo);

    cudaFuncSetAttribute(gemm_mma, cudaFuncAttributeMaxDynamicSharedMemorySize, GEMM_SMEM);
    cudaFuncSetAttribute(flash_kernel, cudaFuncAttributeMaxDynamicSharedMemorySize, 120832);

    // split inputs + weights (weights transposed to [N,K])
    split_rm<<<(S_LEN * DMODEL + 255) / 256, 256>>>(X, xh, xl, S_LEN * DMODEL);
    split_tr<<<dim3(DMODEL / 32, DMODEL / 32), 256>>>(Wq, qh, ql, DMODEL, DMODEL);
    split_tr<<<dim3(KV_DIM / 32, DMODEL / 32), 256>>>(Wk, kh, kl, DMODEL, KV_DIM);
    split_tr<<<dim3(KV_DIM / 32, DMODEL / 32), 256>>>(Wv, vh, vl, DMODEL, KV_DIM);
    split_tr<<<dim3(DMODEL / 32, DMODEL / 32), 256>>>(Wo, wh, wl, DMODEL, DMODEL);

    // QKV projections on tensor cores (mma.sync)
    gemm_mma<<<dim3(DMODEL / 128, S_LEN / 128), 256, GEMM_SMEM>>>(
        xh, xl, qh, ql, gQ, S_LEN, DMODEL, DMODEL);
    gemm_mma<<<dim3(KV_DIM / 128, S_LEN / 128), 256, GEMM_SMEM>>>(
        xh, xl, kh, kl, gK, S_LEN, KV_DIM, DMODEL);
    gemm_mma<<<dim3(KV_DIM / 128, S_LEN / 128), 256, GEMM_SMEM>>>(
        xh, xl, vh, vl, gV, S_LEN, KV_DIM, DMODEL);

    // RoPE
    int rthreads = S_LEN * (NH + NKV) * 64;
    rope_kernel<<<(rthreads + 255) / 256, 256>>>(cosp, sinp);

    // attention (SIMT fp32)
    flash_kernel<<<dim3(S_LEN / 64, NH), 256, 120832>>>();

    // output projection
    split_rm<<<(S_LEN * DMODEL + 255) / 256, 256>>>(gO, oh, ol, S_LEN * DMODEL);
    gemm_mma<<<dim3(DMODEL / 128, S_LEN / 128), 256, GEMM_SMEM>>>(
        oh, ol, wh, wl, out, S_LEN, DMODEL, DMODEL);
}

// round 4
// speedup vs baseline: 3.1183x; 2.3674x over previous
#include <cuda_runtime.h>
#include <cuda_bf16.h>
#include <cstdint>
#include <math.h>

#define S_LEN   4096
#define DMODEL  2048
#define NH      16
#define NKV     4
#define HD      128
#define KV_DIM  (NKV * HD)   // 512

// ---------------- device scratch (allocation-free rule) ----------------
__device__ float g_Q[S_LEN * DMODEL];
__device__ float g_K[S_LEN * KV_DIM];
__device__ float g_V[S_LEN * KV_DIM];

__device__ __nv_bfloat16 g_Xhi[S_LEN * DMODEL];
__device__ __nv_bfloat16 g_Xlo[S_LEN * DMODEL];
__device__ __nv_bfloat16 g_Qhi[S_LEN * DMODEL];
__device__ __nv_bfloat16 g_Qlo[S_LEN * DMODEL];
__device__ __nv_bfloat16 g_Khi[S_LEN * KV_DIM];
__device__ __nv_bfloat16 g_Klo[S_LEN * KV_DIM];
__device__ __nv_bfloat16 g_Vhi[S_LEN * KV_DIM];
__device__ __nv_bfloat16 g_Vlo[S_LEN * KV_DIM];
__device__ __nv_bfloat16 g_Ohi[S_LEN * DMODEL];
__device__ __nv_bfloat16 g_Olo[S_LEN * DMODEL];
__device__ __nv_bfloat16 g_WqThi[DMODEL * DMODEL];
__device__ __nv_bfloat16 g_WqTlo[DMODEL * DMODEL];
__device__ __nv_bfloat16 g_WkThi[KV_DIM * DMODEL];
__device__ __nv_bfloat16 g_WkTlo[KV_DIM * DMODEL];
__device__ __nv_bfloat16 g_WvThi[KV_DIM * DMODEL];
__device__ __nv_bfloat16 g_WvTlo[KV_DIM * DMODEL];
__device__ __nv_bfloat16 g_WoThi[DMODEL * DMODEL];
__device__ __nv_bfloat16 g_WoTlo[DMODEL * DMODEL];

// ---------------- PTX helpers (compute_103-safe: sm_80-era ISA) ----------------
__device__ __forceinline__ uint32_t smem_u32(const void* p) {
    uint32_t a;
    asm("{ .reg .u64 t; cvta.to.shared.u64 t, %1; cvt.u32.u64 %0, t; }"
        : "=r"(a) : "l"(p));
    return a;
}
__device__ __forceinline__ void cp_async16(uint32_t dst, const void* src) {
    asm volatile("cp.async.cg.shared.global [%0], [%1], 16;" :: "r"(dst), "l"(src));
}
#define CP_COMMIT() asm volatile("cp.async.commit_group;" ::: "memory")
#define CP_WAIT(n)  asm volatile("cp.async.wait_group %0;" :: "n"(n) : "memory")

__device__ __forceinline__ void ldm_x4(uint32_t& r0, uint32_t& r1, uint32_t& r2,
                                       uint32_t& r3, uint32_t addr) {
    asm volatile("ldmatrix.sync.aligned.m8n8.x4.shared.b16 {%0,%1,%2,%3}, [%4];"
                 : "=r"(r0), "=r"(r1), "=r"(r2), "=r"(r3) : "r"(addr));
}
__device__ __forceinline__ void ldm_x4_t(uint32_t& r0, uint32_t& r1, uint32_t& r2,
                                         uint32_t& r3, uint32_t addr) {
    asm volatile("ldmatrix.sync.aligned.m8n8.x4.trans.shared.b16 {%0,%1,%2,%3}, [%4];"
                 : "=r"(r0), "=r"(r1), "=r"(r2), "=r"(r3) : "r"(addr));
}
__device__ __forceinline__ void mma_bf16(float& d0, float& d1, float& d2, float& d3,
                                         uint32_t a0, uint32_t a1, uint32_t a2,
                                         uint32_t a3, uint32_t b0, uint32_t b1) {
    asm volatile(
        "mma.sync.aligned.m16n8k16.row.col.f32.bf16.bf16.f32 "
        "{%0,%1,%2,%3}, {%4,%5,%6,%7}, {%8,%9}, {%0,%1,%2,%3};"
        : "+f"(d0), "+f"(d1), "+f"(d2), "+f"(d3)
        : "r"(a0), "r"(a1), "r"(a2), "r"(a3), "r"(b0), "r"(b1));
}
__device__ __forceinline__ uint32_t pack_hi(float x, float y, float& rx, float& ry) {
    __nv_bfloat16 hx = __float2bfloat16(x), hy = __float2bfloat16(y);
    rx = x - __bfloat162float(hx);
    ry = y - __bfloat162float(hy);
    __nv_bfloat162 p(hx, hy);
    return *(uint32_t*)&p;
}
__device__ __forceinline__ uint32_t pack_bf(float x, float y) {
    __nv_bfloat162 p(__float2bfloat16(x), __float2bfloat16(y));
    return *(uint32_t*)&p;
}

// ---------------------------------------------------------------------------
// Split fp32 -> (bf16 hi, bf16 lo)
// ---------------------------------------------------------------------------
__global__ void split_rm(const float* __restrict__ src,
                         __nv_bfloat16* __restrict__ hi,
                         __nv_bfloat16* __restrict__ lo, int n)
{
    int i = blockIdx.x * blockDim.x + threadIdx.x;
    if (i >= n) return;
    float f = src[i];
    __nv_bfloat16 h = __float2bfloat16(f);
    hi[i] = h;
    lo[i] = __float2bfloat16(f - __bfloat162float(h));
}

// ---------------------------------------------------------------------------
// Split + transpose: W[K,N] fp32 -> hiT/loT [N,K] bf16
// ---------------------------------------------------------------------------
__global__ __launch_bounds__(256) void split_tr(const float* __restrict__ W,
                                                __nv_bfloat16* __restrict__ hiT,
                                                __nv_bfloat16* __restrict__ loT,
                                                int K, int N)
{
    __shared__ float s[32][33];
    int n0 = blockIdx.x * 32, k0 = blockIdx.y * 32;
    int tx = threadIdx.x & 31, ty = threadIdx.x >> 5;
    #pragma unroll
    for (int j = 0; j < 4; j++)
        s[ty + j * 8][tx] = W[(size_t)(k0 + ty + j * 8) * N + n0 + tx];
    __syncthreads();
    #pragma unroll
    for (int j = 0; j < 4; j++) {
        int nn = ty + j * 8;
        float f = s[tx][nn];
        __nv_bfloat16 h = __float2bfloat16(f);
        size_t o = (size_t)(n0 + nn) * K + k0 + tx;
        hiT[o] = h;
        loT[o] = __float2bfloat16(f - __bfloat162float(h));
    }
}

// ---------------------------------------------------------------------------
// mma.sync bf16x3 GEMM (R3-verified): C = (Ahi+Alo) @ ((Bhi+Blo)[N,K])^T
// ---------------------------------------------------------------------------
#define GS_TILE   10240
#define GS_STAGE  40960
#define GEMM_SMEM 81920

__global__ __launch_bounds__(256, 2) void gemm_mma(
    const __nv_bfloat16* __restrict__ Ahi, const __nv_bfloat16* __restrict__ Alo,
    const __nv_bfloat16* __restrict__ Bhi, const __nv_bfloat16* __restrict__ Blo,
    float* __restrict__ C, int M, int N, int K)
{
    extern __shared__ char dsm[];
    const uint32_t sbase = smem_u32(dsm);

    const int tid  = threadIdx.x;
    const int lane = tid & 31;
    const int w    = tid >> 5;
    const int wm   = w >> 2;
    const int wn   = w & 3;
    const int n0 = blockIdx.x * 128, m0 = blockIdx.y * 128;

    const __nv_bfloat16* srcs[4] = {
        Ahi + (size_t)m0 * K, Alo + (size_t)m0 * K,
        Bhi + (size_t)n0 * K, Blo + (size_t)n0 * K };

    auto load_stage = [&](int stg, int kk) {
        uint32_t sb = sbase + stg * GS_STAGE;
        #pragma unroll
        for (int it = 0; it < 8; it++) {
            int idx  = it * 256 + tid;
            int tile = idx >> 9;
            int rem  = idx & 511;
            int r    = rem >> 2;
            int c    = rem & 3;
            cp_async16(sb + tile * GS_TILE + r * 80 + c * 16,
                       srcs[tile] + (size_t)r * K + kk + c * 8);
        }
        CP_COMMIT();
    };

    float acc[4][4][4];
    #pragma unroll
    for (int i = 0; i < 4; i++)
        #pragma unroll
        for (int j = 0; j < 4; j++)
            #pragma unroll
            for (int q = 0; q < 4; q++) acc[i][j][q] = 0.f;

    const int ns = K >> 5;
    load_stage(0, 0);

    for (int i = 0; i < ns; i++) {
        if (i + 1 < ns) { load_stage((i + 1) & 1, (i + 1) * 32); CP_WAIT(1); }
        else            { CP_WAIT(0); }
        __syncthreads();

        const uint32_t sb  = sbase + (i & 1) * GS_STAGE;
        const uint32_t ldr = (lane & 15);
        const uint32_t ldc = (lane >> 4) * 16;

        #pragma unroll
        for (int ks = 0; ks < 2; ks++) {
            const uint32_t kboff = ks * 32 + ldc;
            uint32_t af[2][4][4];
            #pragma unroll
            for (int p = 0; p < 2; p++)
                #pragma unroll
                for (int mt = 0; mt < 4; mt++)
                    ldm_x4(af[p][mt][0], af[p][mt][1], af[p][mt][2], af[p][mt][3],
                           sb + p * GS_TILE +
                           (wm * 64 + mt * 16 + ldr) * 80 + kboff);

            #pragma unroll
            for (int nh = 0; nh < 2; nh++) {
                uint32_t bf[2][4];
                #pragma unroll
                for (int p = 0; p < 2; p++)
                    ldm_x4(bf[p][0], bf[p][1], bf[p][2], bf[p][3],
                           sb + (2 + p) * GS_TILE +
                           (wn * 32 + nh * 16 + ldr) * 80 + kboff);

                #pragma unroll
                for (int mt = 0; mt < 4; mt++) {
                    #pragma unroll
                    for (int sub = 0; sub < 2; sub++) {
                        const int nt = nh * 2 + sub;
                        float* d = acc[mt][nt];
                        mma_bf16(d[0], d[1], d[2], d[3],
                                 af[0][mt][0], af[0][mt][1], af[0][mt][2], af[0][mt][3],
                                 bf[0][sub], bf[0][sub + 2]);
                        mma_bf16(d[0], d[1], d[2], d[3],
                                 af[0][mt][0], af[0][mt][1], af[0][mt][2], af[0][mt][3],
                                 bf[1][sub], bf[1][sub + 2]);
                        mma_bf16(d[0], d[1], d[2], d[3],
                                 af[1][mt][0], af[1][mt][1], af[1][mt][2], af[1][mt][3],
                                 bf[0][sub], bf[0][sub + 2]);
                    }
                }
            }
        }
        __syncthreads();
    }

    const int trow = lane >> 2;
    const int tcol = (lane & 3) * 2;
    #pragma unroll
    for (int mt = 0; mt < 4; mt++) {
        #pragma unroll
        for (int nt = 0; nt < 4; nt++) {
            const int rr = m0 + wm * 64 + mt * 16 + trow;
            const int cc = n0 + wn * 32 + nt * 8 + tcol;
            *(float2*)&C[(size_t)rr * N + cc] =
                make_float2(acc[mt][nt][0], acc[mt][nt][1]);
            *(float2*)&C[(size_t)(rr + 8) * N + cc] =
                make_float2(acc[mt][nt][2], acc[mt][nt][3]);
        }
    }
}

// ---------------------------------------------------------------------------
// RoPE + split: reads fp32 g_Q/g_K, writes bf16 hi/lo planes
// ---------------------------------------------------------------------------
__global__ void rope_split(const float* __restrict__ cosp,
                           const float* __restrict__ sinp)
{
    const int per_s = (NH + NKV) * 64;
    int idx = blockIdx.x * blockDim.x + threadIdx.x;
    if (idx >= S_LEN * per_s) return;
    int s = idx / per_s;
    int r = idx % per_s;
    int hh = r >> 6;
    int d = r & 63;

    const float* p;
    __nv_bfloat16 *dh, *dl;
    size_t off;
    if (hh < NH) {
        off = (size_t)s * DMODEL + hh * HD;
        p = g_Q + off; dh = g_Qhi + off; dl = g_Qlo + off;
    } else {
        off = (size_t)s * KV_DIM + (hh - NH) * HD;
        p = g_K + off; dh = g_Khi + off; dl = g_Klo + off;
    }

    float c0 = cosp[s * HD + d],      s0 = sinp[s * HD + d];
    float c1 = cosp[s * HD + d + 64], s1 = sinp[s * HD + d + 64];
    float x0 = p[d], x1 = p[d + 64];
    float y0 = x0 * c0 - x1 * s0;
    float y1 = x1 * c1 + x0 * s1;

    __nv_bfloat16 h0 = __float2bfloat16(y0);
    __nv_bfloat16 h1 = __float2bfloat16(y1);
    dh[d] = h0;      dl[d] = __float2bfloat16(y0 - __bfloat162float(h0));
    dh[d + 64] = h1; dl[d + 64] = __float2bfloat16(y1 - __bfloat162float(h1));
}

// ---------------------------------------------------------------------------
// Tensor-core flash attention (bf16x3, fp32 softmax/accum), causal.
// CTA: 128 q-rows x 1 head, 8 warps (16 rows each, full key stripe).
// BN=64 keys/iter; K/V hi+lo double-buffered cp.async; Q resident in smem.
// ---------------------------------------------------------------------------
#define FS_STRIDE   272                 // 128 bf16 + 16B pad
#define FS_Q_PLANE  (128 * FS_STRIDE)   // 34816
#define FS_KV_PLANE (64 * FS_STRIDE)    // 17408
#define FS_STAGE    (4 * FS_KV_PLANE)   // 69632: Khi,Klo,Vhi,Vlo
#define FLASH_SMEM  (2 * FS_Q_PLANE + 2 * FS_STAGE)   // 208896

__global__ __launch_bounds__(256, 1) void flash_mma()
{
    extern __shared__ char dsm[];
    const uint32_t sb = smem_u32(dsm);
    const uint32_t sQ = sb;                       // 2 planes
    const uint32_t sS = sb + 2 * FS_Q_PLANE;      // stages

    const int tid = threadIdx.x, lane = tid & 31, w = tid >> 5;
    const int qb = gridDim.x - 1 - blockIdx.x;    // heavy first
    const int h  = blockIdx.y;
    const int kvh = h >> 2;
    const int q0 = qb * 128;
    const float scale = 0.08838834764831845f;

    // ---- Q load (2 planes x 128 rows x 16 chunks) ----
    {
        const __nv_bfloat16* qsrc[2] = { g_Qhi, g_Qlo };
        #pragma unroll
        for (int it = 0; it < 16; it++) {
            int idx = it * 256 + tid;
            int pl = idx >> 11, rem = idx & 2047;
            int r = rem >> 4, c = rem & 15;
            cp_async16(sQ + pl * FS_Q_PLANE + r * FS_STRIDE + c * 16,
                       qsrc[pl] + (size_t)(q0 + r) * DMODEL + h * HD + c * 8);
        }
    }
    // ---- stage loader ----
    auto load_stage = [&](int stg, int k0) {
        const __nv_bfloat16* src[4] = { g_Khi, g_Klo, g_Vhi, g_Vlo };
        uint32_t base = sS + stg * FS_STAGE;
        #pragma unroll
        for (int it = 0; it < 16; it++) {
            int idx = it * 256 + tid;
            int tile = idx >> 10, rem = idx & 1023;
            int r = rem >> 4, c = rem & 15;
            cp_async16(base + tile * FS_KV_PLANE + r * FS_STRIDE + c * 16,
                       src[tile] + (size_t)(k0 + r) * KV_DIM + kvh * HD + c * 8);
        }
    };
    load_stage(0, 0);
    CP_COMMIT();

    float o[16][4];
    #pragma unroll
    for (int t = 0; t < 16; t++)
        #pragma unroll
        for (int e = 0; e < 4; e++) o[t][e] = 0.f;
    float m0 = -1e30f, m1 = -1e30f, l0 = 0.f, l1 = 0.f;

    const uint32_t ldrow = lane & 15;
    const uint32_t ldoff = (lane >> 4) * 16;
    const int niter = 2 * qb + 2;
    const int rlow = q0 + w * 16 + (lane >> 2);

    for (int kb = 0; kb < niter; kb++) {
        if (kb + 1 < niter) { load_stage((kb + 1) & 1, (kb + 1) * 64); CP_COMMIT(); CP_WAIT(1); }
        else                { CP_WAIT(0); }
        __syncthreads();

        const uint32_t st = sS + (kb & 1) * FS_STAGE;

        // ---- S = Q K^T (16x64 per warp) ----
        float s_acc[8][4];
        #pragma unroll
        for (int t = 0; t < 8; t++)
            #pragma unroll
            for (int e = 0; e < 4; e++) s_acc[t][e] = 0.f;

        #pragma unroll
        for (int kt = 0; kt < 8; kt++) {
            uint32_t qaddr = sQ + (w * 16 + ldrow) * FS_STRIDE + kt * 32 + ldoff;
            uint32_t qh_[4], ql_[4];
            ldm_x4(qh_[0], qh_[1], qh_[2], qh_[3], qaddr);
            ldm_x4(ql_[0], ql_[1], ql_[2], ql_[3], qaddr + FS_Q_PLANE);
            #pragma unroll
            for (int nt2 = 0; nt2 < 4; nt2++) {
                uint32_t kaddr = st + (nt2 * 16 + ldrow) * FS_STRIDE + kt * 32 + ldoff;
                uint32_t kh_[4], kl_[4];
                ldm_x4(kh_[0], kh_[1], kh_[2], kh_[3], kaddr);
                ldm_x4(kl_[0], kl_[1], kl_[2], kl_[3], kaddr + FS_KV_PLANE);
                #pragma unroll
                for (int sub = 0; sub < 2; sub++) {
                    float* d = s_acc[nt2 * 2 + sub];
                    mma_bf16(d[0], d[1], d[2], d[3],
                             qh_[0], qh_[1], qh_[2], qh_[3], kh_[sub], kh_[sub + 2]);
                    mma_bf16(d[0], d[1], d[2], d[3],
                             qh_[0], qh_[1], qh_[2], qh_[3], kl_[sub], kl_[sub + 2]);
                    mma_bf16(d[0], d[1], d[2], d[3],
                             ql_[0], ql_[1], ql_[2], ql_[3], kh_[sub], kh_[sub + 2]);
                }
            }
        }

        // ---- scale + causal mask ----
        const bool needmask = (kb >= 2 * qb);
        const int colb = kb * 64 + (lane & 3) * 2;
        #pragma unroll
        for (int t = 0; t < 8; t++) {
            #pragma unroll
            for (int e = 0; e < 4; e++) {
                float v = s_acc[t][e] * scale;
                if (needmask) {
                    int col = colb + t * 8 + (e & 1);
                    int row = rlow + ((e >= 2) ? 8 : 0);
                    if (col > row) v = -1e30f;
                }
                s_acc[t][e] = v;
            }
        }

        // ---- online softmax (rows rlow, rlow+8) ----
        float rmax0 = -1e30f, rmax1 = -1e30f;
        #pragma unroll
        for (int t = 0; t < 8; t++) {
            rmax0 = fmaxf(rmax0, fmaxf(s_acc[t][0], s_acc[t][1]));
            rmax1 = fmaxf(rmax1, fmaxf(s_acc[t][2], s_acc[t][3]));
        }
        #pragma unroll
        for (int off = 1; off <= 2; off <<= 1) {
            rmax0 = fmaxf(rmax0, __shfl_xor_sync(0xffffffffu, rmax0, off));
            rmax1 = fmaxf(rmax1, __shfl_xor_sync(0xffffffffu, rmax1, off));
        }
        float mn0 = fmaxf(m0, rmax0), mn1 = fmaxf(m1, rmax1);
        float al0 = __expf(m0 - mn0), al1 = __expf(m1 - mn1);
        float sum0 = 0.f, sum1 = 0.f;
        #pragma unroll
        for (int t = 0; t < 8; t++) {
            float p0 = __expf(s_acc[t][0] - mn0);
            float p1 = __expf(s_acc[t][1] - mn0);
            float p2 = __expf(s_acc[t][2] - mn1);
            float p3 = __expf(s_acc[t][3] - mn1);
            s_acc[t][0] = p0; s_acc[t][1] = p1; s_acc[t][2] = p2; s_acc[t][3] = p3;
            sum0 += p0 + p1; sum1 += p2 + p3;
        }
        #pragma unroll
        for (int off = 1; off <= 2; off <<= 1) {
            sum0 += __shfl_xor_sync(0xffffffffu, sum0, off);
            sum1 += __shfl_xor_sync(0xffffffffu, sum1, off);
        }
        l0 = l0 * al0 + sum0;  m0 = mn0;
        l1 = l1 * al1 + sum1;  m1 = mn1;
        #pragma unroll
        for (int t = 0; t < 16; t++) {
            o[t][0] *= al0; o[t][1] *= al0;
            o[t][2] *= al1; o[t][3] *= al1;
        }

        // ---- O += P V ----
        #pragma unroll
        for (int j = 0; j < 4; j++) {
            float lx[8];
            uint32_t ah[4], alr[4];
            ah[0] = pack_hi(s_acc[2*j][0],   s_acc[2*j][1],   lx[0], lx[1]);
            ah[1] = pack_hi(s_acc[2*j][2],   s_acc[2*j][3],   lx[2], lx[3]);
            ah[2] = pack_hi(s_acc[2*j+1][0], s_acc[2*j+1][1], lx[4], lx[5]);
            ah[3] = pack_hi(s_acc[2*j+1][2], s_acc[2*j+1][3], lx[6], lx[7]);
            alr[0] = pack_bf(lx[0], lx[1]);
            alr[1] = pack_bf(lx[2], lx[3]);
            alr[2] = pack_bf(lx[4], lx[5]);
            alr[3] = pack_bf(lx[6], lx[7]);

            #pragma unroll
            for (int dt2 = 0; dt2 < 8; dt2++) {
                uint32_t vaddr = st + 2 * FS_KV_PLANE +
                                 (j * 16 + ldrow) * FS_STRIDE + dt2 * 32 + ldoff;
                uint32_t vh_[4], vl_[4];
                ldm_x4_t(vh_[0], vh_[1], vh_[2], vh_[3], vaddr);
                ldm_x4_t(vl_[0], vl_[1], vl_[2], vl_[3], vaddr + FS_KV_PLANE);
                #pragma unroll
                for (int sub = 0; sub < 2; sub++) {
                    float* d = o[dt2 * 2 + sub];
                    mma_bf16(d[0], d[1], d[2], d[3],
                             ah[0], ah[1], ah[2], ah[3], vh_[2*sub], vh_[2*sub+1]);
                    mma_bf16(d[0], d[1], d[2], d[3],
                             ah[0], ah[1], ah[2], ah[3], vl_[2*sub], vl_[2*sub+1]);
                    mma_bf16(d[0], d[1], d[2], d[3],
                             alr[0], alr[1], alr[2], alr[3], vh_[2*sub], vh_[2*sub+1]);
                }
            }
        }
        __syncthreads();   // all warps done with stage kb before next prefetch overwrites
    }

    // ---- normalize + direct bf16 hi/lo store ----
    float inv0 = 1.0f / l0, inv1 = 1.0f / l1;
    const int row0 = q0 + w * 16 + (lane >> 2);
    #pragma unroll
    for (int t = 0; t < 16; t++) {
        int d = t * 8 + (lane & 3) * 2;
        size_t off0 = (size_t)row0 * DMODEL + h * HD + d;
        size_t off1 = off0 + 8 * DMODEL;
        float v0 = o[t][0] * inv0, v1 = o[t][1] * inv0;
        float v2 = o[t][2] * inv1, v3 = o[t][3] * inv1;
        __nv_bfloat16 h0 = __float2bfloat16(v0), h1 = __float2bfloat16(v1);
        __nv_bfloat16 h2 = __float2bfloat16(v2), h3 = __float2bfloat16(v3);
        *(__nv_bfloat162*)&g_Ohi[off0] = __nv_bfloat162(h0, h1);
        *(__nv_bfloat162*)&g_Ohi[off1] = __nv_bfloat162(h2, h3);
        *(__nv_bfloat162*)&g_Olo[off0] = __nv_bfloat162(
            __float2bfloat16(v0 - __bfloat162float(h0)),
            __float2bfloat16(v1 - __bfloat162float(h1)));
        *(__nv_bfloat162*)&g_Olo[off1] = __nv_bfloat162(
            __float2bfloat16(v2 - __bfloat162float(h2)),
            __float2bfloat16(v3 - __bfloat162float(h3)));
    }
}

// ---------------------------------------------------------------------------
extern "C" void kernel_launch(void* const* d_in, const int* in_sizes, int n_in,
                              void* d_out, int out_size)
{
    const float* X    = (const float*)d_in[0];
    const float* cosp = (const float*)d_in[1];
    const float* sinp = (const float*)d_in[2];
    const float* Wq   = (const float*)d_in[3];
    const float* Wk   = (const float*)d_in[4];
    const float* Wv   = (const float*)d_in[5];
    const float* Wo   = (const float*)d_in[6];
    float* out = (float*)d_out;

    float *gQ, *gK, *gV;
    cudaGetSymbolAddress((void**)&gQ, g_Q);
    cudaGetSymbolAddress((void**)&gK, g_K);
    cudaGetSymbolAddress((void**)&gV, g_V);
    __nv_bfloat16 *xh, *xl, *oh, *ol, *qh, *ql, *kh, *kl, *vh, *vl, *wh, *wl;
    __nv_bfloat16 *gvh, *gvl;
    cudaGetSymbolAddress((void**)&xh, g_Xhi);  cudaGetSymbolAddress((void**)&xl, g_Xlo);
    cudaGetSymbolAddress((void**)&oh, g_Ohi);  cudaGetSymbolAddress((void**)&ol, g_Olo);
    cudaGetSymbolAddress((void**)&gvh, g_Vhi); cudaGetSymbolAddress((void**)&gvl, g_Vlo);
    cudaGetSymbolAddress((void**)&qh, g_WqThi); cudaGetSymbolAddress((void**)&ql, g_WqTlo);
    cudaGetSymbolAddress((void**)&kh, g_WkThi); cudaGetSymbolAddress((void**)&kl, g_WkTlo);
    cudaGetSymbolAddress((void**)&vh, g_WvThi); cudaGetSymbolAddress((void**)&vl, g_WvTlo);
    cudaGetSymbolAddress((void**)&wh, g_WoThi); cudaGetSymbolAddress((void**)&wl, g_WoTlo);

    cudaFuncSetAttribute(gemm_mma, cudaFuncAttributeMaxDynamicSharedMemorySize, GEMM_SMEM);
    cudaFuncSetAttribute(flash_mma, cudaFuncAttributeMaxDynamicSharedMemorySize, FLASH_SMEM);

    // splits
    split_rm<<<(S_LEN * DMODEL + 255) / 256, 256>>>(X, xh, xl, S_LEN * DMODEL);
    split_tr<<<dim3(DMODEL / 32, DMODEL / 32), 256>>>(Wq, qh, ql, DMODEL, DMODEL);
    split_tr<<<dim3(KV_DIM / 32, DMODEL / 32), 256>>>(Wk, kh, kl, DMODEL, KV_DIM);
    split_tr<<<dim3(KV_DIM / 32, DMODEL / 32), 256>>>(Wv, vh, vl, DMODEL, KV_DIM);
    split_tr<<<dim3(DMODEL / 32, DMODEL / 32), 256>>>(Wo, wh, wl, DMODEL, DMODEL);

    // QKV projections (tensor core)
    gemm_mma<<<dim3(DMODEL / 128, S_LEN / 128), 256, GEMM_SMEM>>>(
        xh, xl, qh, ql, gQ, S_LEN, DMODEL, DMODEL);
    gemm_mma<<<dim3(KV_DIM / 128, S_LEN / 128), 256, GEMM_SMEM>>>(
        xh, xl, kh, kl, gK, S_LEN, KV_DIM, DMODEL);
    gemm_mma<<<dim3(KV_DIM / 128, S_LEN / 128), 256, GEMM_SMEM>>>(
        xh, xl, vh, vl, gV, S_LEN, KV_DIM, DMODEL);

    // RoPE -> bf16 planes; V -> bf16 planes
    int rthreads = S_LEN * (NH + NKV) * 64;
    rope_split<<<(rthreads + 255) / 256, 256>>>(cosp, sinp);
    split_rm<<<(S_LEN * KV_DIM + 255) / 256, 256>>>(gV, gvh, gvl, S_LEN * KV_DIM);

    // tensor-core flash attention (writes g_Ohi/g_Olo directly)
    flash_mma<<<dim3(S_LEN / 128, NH), 256, FLASH_SMEM>>>();

    // output projection
    gemm_mma<<<dim3(DMODEL / 128, S_LEN / 128), 256, GEMM_SMEM>>>(
        oh, ol, wh, wl, out, S_LEN, DMODEL, DMODEL);
}

// round 6
// speedup vs baseline: 3.1254x; 1.0023x over previous
#include <cuda_runtime.h>
#include <cuda_bf16.h>
#include <cstdint>
#include <math.h>

#define S_LEN   4096
#define DMODEL  2048
#define NH      16
#define NKV     4
#define HD      128
#define KV_DIM  (NKV * HD)   // 512

// ---------------- device scratch (allocation-free rule) ----------------
__device__ float g_Q[S_LEN * DMODEL];
__device__ float g_K[S_LEN * KV_DIM];
__device__ float g_V[S_LEN * KV_DIM];

__device__ __nv_bfloat16 g_Xhi[S_LEN * DMODEL];
__device__ __nv_bfloat16 g_Xlo[S_LEN * DMODEL];
__device__ __nv_bfloat16 g_Qhi[S_LEN * DMODEL];
__device__ __nv_bfloat16 g_Qlo[S_LEN * DMODEL];
__device__ __nv_bfloat16 g_Khi[S_LEN * KV_DIM];
__device__ __nv_bfloat16 g_Klo[S_LEN * KV_DIM];
__device__ __nv_bfloat16 g_Vhi[S_LEN * KV_DIM];
__device__ __nv_bfloat16 g_Vlo[S_LEN * KV_DIM];
__device__ __nv_bfloat16 g_Ohi[S_LEN * DMODEL];
__device__ __nv_bfloat16 g_Olo[S_LEN * DMODEL];
__device__ __nv_bfloat16 g_WqThi[DMODEL * DMODEL];
__device__ __nv_bfloat16 g_WqTlo[DMODEL * DMODEL];
__device__ __nv_bfloat16 g_WkThi[KV_DIM * DMODEL];
__device__ __nv_bfloat16 g_WkTlo[KV_DIM * DMODEL];
__device__ __nv_bfloat16 g_WvThi[KV_DIM * DMODEL];
__device__ __nv_bfloat16 g_WvTlo[KV_DIM * DMODEL];
__device__ __nv_bfloat16 g_WoThi[DMODEL * DMODEL];
__device__ __nv_bfloat16 g_WoTlo[DMODEL * DMODEL];

// ---------------- PTX helpers (compute_103-safe: sm_80-era ISA) ----------------
__device__ __forceinline__ uint32_t smem_u32(const void* p) {
    uint32_t a;
    asm("{ .reg .u64 t; cvta.to.shared.u64 t, %1; cvt.u32.u64 %0, t; }"
        : "=r"(a) : "l"(p));
    return a;
}
__device__ __forceinline__ void cp_async16(uint32_t dst, const void* src) {
    asm volatile("cp.async.cg.shared.global [%0], [%1], 16;" :: "r"(dst), "l"(src));
}
#define CP_COMMIT() asm volatile("cp.async.commit_group;" ::: "memory")
#define CP_WAIT(n)  asm volatile("cp.async.wait_group %0;" :: "n"(n) : "memory")

__device__ __forceinline__ void ldm_x4(uint32_t& r0, uint32_t& r1, uint32_t& r2,
                                       uint32_t& r3, uint32_t addr) {
    asm volatile("ldmatrix.sync.aligned.m8n8.x4.shared.b16 {%0,%1,%2,%3}, [%4];"
                 : "=r"(r0), "=r"(r1), "=r"(r2), "=r"(r3) : "r"(addr));
}
__device__ __forceinline__ void ldm_x4_t(uint32_t& r0, uint32_t& r1, uint32_t& r2,
                                         uint32_t& r3, uint32_t addr) {
    asm volatile("ldmatrix.sync.aligned.m8n8.x4.trans.shared.b16 {%0,%1,%2,%3}, [%4];"
                 : "=r"(r0), "=r"(r1), "=r"(r2), "=r"(r3) : "r"(addr));
}
__device__ __forceinline__ void mma_bf16(float& d0, float& d1, float& d2, float& d3,
                                         uint32_t a0, uint32_t a1, uint32_t a2,
                                         uint32_t a3, uint32_t b0, uint32_t b1) {
    asm volatile(
        "mma.sync.aligned.m16n8k16.row.col.f32.bf16.bf16.f32 "
        "{%0,%1,%2,%3}, {%4,%5,%6,%7}, {%8,%9}, {%0,%1,%2,%3};"
        : "+f"(d0), "+f"(d1), "+f"(d2), "+f"(d3)
        : "r"(a0), "r"(a1), "r"(a2), "r"(a3), "r"(b0), "r"(b1));
}
__device__ __forceinline__ uint32_t pack_hi(float x, float y, float& rx, float& ry) {
    __nv_bfloat16 hx = __float2bfloat16(x), hy = __float2bfloat16(y);
    rx = x - __bfloat162float(hx);
    ry = y - __bfloat162float(hy);
    __nv_bfloat162 p(hx, hy);
    return *(uint32_t*)&p;
}
__device__ __forceinline__ uint32_t pack_bf(float x, float y) {
    __nv_bfloat162 p(__float2bfloat16(x), __float2bfloat16(y));
    return *(uint32_t*)&p;
}

// ---------------------------------------------------------------------------
// Split fp32 -> (bf16 hi, bf16 lo)
// ---------------------------------------------------------------------------
__global__ void split_rm(const float* __restrict__ src,
                         __nv_bfloat16* __restrict__ hi,
                         __nv_bfloat16* __restrict__ lo, int n)
{
    int i = blockIdx.x * blockDim.x + threadIdx.x;
    if (i >= n) return;
    float f = src[i];
    __nv_bfloat16 h = __float2bfloat16(f);
    hi[i] = h;
    lo[i] = __float2bfloat16(f - __bfloat162float(h));
}

// ---------------------------------------------------------------------------
// Split + transpose: W[K,N] fp32 -> hiT/loT [N,K] bf16
// ---------------------------------------------------------------------------
__global__ __launch_bounds__(256) void split_tr(const float* __restrict__ W,
                                                __nv_bfloat16* __restrict__ hiT,
                                                __nv_bfloat16* __restrict__ loT,
                                                int K, int N)
{
    __shared__ float s[32][33];
    int n0 = blockIdx.x * 32, k0 = blockIdx.y * 32;
    int tx = threadIdx.x & 31, ty = threadIdx.x >> 5;
    #pragma unroll
    for (int j = 0; j < 4; j++)
        s[ty + j * 8][tx] = W[(size_t)(k0 + ty + j * 8) * N + n0 + tx];
    __syncthreads();
    #pragma unroll
    for (int j = 0; j < 4; j++) {
        int nn = ty + j * 8;
        float f = s[tx][nn];
        __nv_bfloat16 h = __float2bfloat16(f);
        size_t o = (size_t)(n0 + nn) * K + k0 + tx;
        hiT[o] = h;
        loT[o] = __float2bfloat16(f - __bfloat162float(h));
    }
}

// ---------------------------------------------------------------------------
// mma.sync bf16x3 GEMM: C = (Ahi+Alo) @ ((Bhi+Blo)[N,K])^T
// Plane-term loop outermost -> 8 independent accumulators between reuse.
// ---------------------------------------------------------------------------
#define GS_TILE   10240
#define GS_STAGE  40960
#define GEMM_SMEM 81920

__global__ __launch_bounds__(256, 2) void gemm_mma(
    const __nv_bfloat16* __restrict__ Ahi, const __nv_bfloat16* __restrict__ Alo,
    const __nv_bfloat16* __restrict__ Bhi, const __nv_bfloat16* __restrict__ Blo,
    float* __restrict__ C, int M, int N, int K)
{
    extern __shared__ char dsm[];
    const uint32_t sbase = smem_u32(dsm);

    const int tid  = threadIdx.x;
    const int lane = tid & 31;
    const int w    = tid >> 5;
    const int wm   = w >> 2;
    const int wn   = w & 3;
    const int n0 = blockIdx.x * 128, m0 = blockIdx.y * 128;

    const __nv_bfloat16* srcs[4] = {
        Ahi + (size_t)m0 * K, Alo + (size_t)m0 * K,
        Bhi + (size_t)n0 * K, Blo + (size_t)n0 * K };

    auto load_stage = [&](int stg, int kk) {
        uint32_t sb = sbase + stg * GS_STAGE;
        #pragma unroll
        for (int it = 0; it < 8; it++) {
            int idx  = it * 256 + tid;
            int tile = idx >> 9;
            int rem  = idx & 511;
            int r    = rem >> 2;
            int c    = rem & 3;
            cp_async16(sb + tile * GS_TILE + r * 80 + c * 16,
                       srcs[tile] + (size_t)r * K + kk + c * 8);
        }
        CP_COMMIT();
    };

    float acc[4][4][4];
    #pragma unroll
    for (int i = 0; i < 4; i++)
        #pragma unroll
        for (int j = 0; j < 4; j++)
            #pragma unroll
            for (int q = 0; q < 4; q++) acc[i][j][q] = 0.f;

    const int ns = K >> 5;
    load_stage(0, 0);

    for (int i = 0; i < ns; i++) {
        if (i + 1 < ns) { load_stage((i + 1) & 1, (i + 1) * 32); CP_WAIT(1); }
        else            { CP_WAIT(0); }
        __syncthreads();

        const uint32_t sb  = sbase + (i & 1) * GS_STAGE;
        const uint32_t ldr = (lane & 15);
        const uint32_t ldc = (lane >> 4) * 16;

        #pragma unroll
        for (int ks = 0; ks < 2; ks++) {
            const uint32_t kboff = ks * 32 + ldc;
            uint32_t af[2][4][4];
            #pragma unroll
            for (int p = 0; p < 2; p++)
                #pragma unroll
                for (int mt = 0; mt < 4; mt++)
                    ldm_x4(af[p][mt][0], af[p][mt][1], af[p][mt][2], af[p][mt][3],
                           sb + p * GS_TILE +
                           (wm * 64 + mt * 16 + ldr) * 80 + kboff);

            #pragma unroll
            for (int nh = 0; nh < 2; nh++) {
                uint32_t bf[2][4];
                #pragma unroll
                for (int p = 0; p < 2; p++)
                    ldm_x4(bf[p][0], bf[p][1], bf[p][2], bf[p][3],
                           sb + (2 + p) * GS_TILE +
                           (wn * 32 + nh * 16 + ldr) * 80 + kboff);

                // term 0: hi*hi  (8 independent accumulators)
                #pragma unroll
                for (int mt = 0; mt < 4; mt++)
                    #pragma unroll
                    for (int sub = 0; sub < 2; sub++) {
                        float* d = acc[mt][nh * 2 + sub];
                        mma_bf16(d[0], d[1], d[2], d[3],
                                 af[0][mt][0], af[0][mt][1], af[0][mt][2], af[0][mt][3],
                                 bf[0][sub], bf[0][sub + 2]);
                    }
                // term 1: hi*lo
                #pragma unroll
                for (int mt = 0; mt < 4; mt++)
                    #pragma unroll
                    for (int sub = 0; sub < 2; sub++) {
                        float* d = acc[mt][nh * 2 + sub];
                        mma_bf16(d[0], d[1], d[2], d[3],
                                 af[0][mt][0], af[0][mt][1], af[0][mt][2], af[0][mt][3],
                                 bf[1][sub], bf[1][sub + 2]);
                    }
                // term 2: lo*hi
                #pragma unroll
                for (int mt = 0; mt < 4; mt++)
                    #pragma unroll
                    for (int sub = 0; sub < 2; sub++) {
                        float* d = acc[mt][nh * 2 + sub];
                        mma_bf16(d[0], d[1], d[2], d[3],
                                 af[1][mt][0], af[1][mt][1], af[1][mt][2], af[1][mt][3],
                                 bf[0][sub], bf[0][sub + 2]);
                    }
            }
        }
        __syncthreads();
    }

    const int trow = lane >> 2;
    const int tcol = (lane & 3) * 2;
    #pragma unroll
    for (int mt = 0; mt < 4; mt++) {
        #pragma unroll
        for (int nt = 0; nt < 4; nt++) {
            const int rr = m0 + wm * 64 + mt * 16 + trow;
            const int cc = n0 + wn * 32 + nt * 8 + tcol;
            *(float2*)&C[(size_t)rr * N + cc] =
                make_float2(acc[mt][nt][0], acc[mt][nt][1]);
            *(float2*)&C[(size_t)(rr + 8) * N + cc] =
                make_float2(acc[mt][nt][2], acc[mt][nt][3]);
        }
    }
}

// ---------------------------------------------------------------------------
// RoPE + split: reads fp32 g_Q/g_K, writes bf16 hi/lo planes
// ---------------------------------------------------------------------------
__global__ void rope_split(const float* __restrict__ cosp,
                           const float* __restrict__ sinp)
{
    const int per_s = (NH + NKV) * 64;
    int idx = blockIdx.x * blockDim.x + threadIdx.x;
    if (idx >= S_LEN * per_s) return;
    int s = idx / per_s;
    int r = idx % per_s;
    int hh = r >> 6;
    int d = r & 63;

    const float* p;
    __nv_bfloat16 *dh, *dl;
    size_t off;
    if (hh < NH) {
        off = (size_t)s * DMODEL + hh * HD;
        p = g_Q + off; dh = g_Qhi + off; dl = g_Qlo + off;
    } else {
        off = (size_t)s * KV_DIM + (hh - NH) * HD;
        p = g_K + off; dh = g_Khi + off; dl = g_Klo + off;
    }

    float c0 = cosp[s * HD + d],      s0 = sinp[s * HD + d];
    float c1 = cosp[s * HD + d + 64], s1 = sinp[s * HD + d + 64];
    float x0 = p[d], x1 = p[d + 64];
    float y0 = x0 * c0 - x1 * s0;
    float y1 = x1 * c1 + x0 * s1;

    __nv_bfloat16 h0 = __float2bfloat16(y0);
    __nv_bfloat16 h1 = __float2bfloat16(y1);
    dh[d] = h0;      dl[d] = __float2bfloat16(y0 - __bfloat162float(h0));
    dh[d + 64] = h1; dl[d + 64] = __float2bfloat16(y1 - __bfloat162float(h1));
}

// ---------------------------------------------------------------------------
// Tensor-core flash attention (bf16x3, fp32 softmax/accum), causal.
// CTA: 128 q-rows x 1 head, 8 warps (16 rows each, full key stripe).
// ---------------------------------------------------------------------------
#define FS_STRIDE   272
#define FS_Q_PLANE  (128 * FS_STRIDE)
#define FS_KV_PLANE (64 * FS_STRIDE)
#define FS_STAGE    (4 * FS_KV_PLANE)
#define FLASH_SMEM  (2 * FS_Q_PLANE + 2 * FS_STAGE)   // 208896

__global__ __launch_bounds__(256, 1) void flash_mma()
{
    extern __shared__ char dsm[];
    const uint32_t sb = smem_u32(dsm);
    const uint32_t sQ = sb;
    const uint32_t sS = sb + 2 * FS_Q_PLANE;

    const int tid = threadIdx.x, lane = tid & 31, w = tid >> 5;
    const int qb = gridDim.x - 1 - blockIdx.x;
    const int h  = blockIdx.y;
    const int kvh = h >> 2;
    const int q0 = qb * 128;
    const float scale = 0.08838834764831845f;

    {
        const __nv_bfloat16* qsrc[2] = { g_Qhi, g_Qlo };
        #pragma unroll
        for (int it = 0; it < 16; it++) {
            int idx = it * 256 + tid;
            int pl = idx >> 11, rem = idx & 2047;
            int r = rem >> 4, c = rem & 15;
            cp_async16(sQ + pl * FS_Q_PLANE + r * FS_STRIDE + c * 16,
                       qsrc[pl] + (size_t)(q0 + r) * DMODEL + h * HD + c * 8);
        }
    }
    auto load_stage = [&](int stg, int k0) {
        const __nv_bfloat16* src[4] = { g_Khi, g_Klo, g_Vhi, g_Vlo };
        uint32_t base = sS + stg * FS_STAGE;
        #pragma unroll
        for (int it = 0; it < 16; it++) {
            int idx = it * 256 + tid;
            int tile = idx >> 10, rem = idx & 1023;
            int r = rem >> 4, c = rem & 15;
            cp_async16(base + tile * FS_KV_PLANE + r * FS_STRIDE + c * 16,
                       src[tile] + (size_t)(k0 + r) * KV_DIM + kvh * HD + c * 8);
        }
    };
    load_stage(0, 0);
    CP_COMMIT();

    float o[16][4];
    #pragma unroll
    for (int t = 0; t < 16; t++)
        #pragma unroll
        for (int e = 0; e < 4; e++) o[t][e] = 0.f;
    float m0 = -1e30f, m1 = -1e30f, l0 = 0.f, l1 = 0.f;

    const uint32_t ldrow = lane & 15;
    const uint32_t ldoff = (lane >> 4) * 16;
    const int niter = 2 * qb + 2;
    const int rlow = q0 + w * 16 + (lane >> 2);

    for (int kb = 0; kb < niter; kb++) {
        if (kb + 1 < niter) { load_stage((kb + 1) & 1, (kb + 1) * 64); CP_COMMIT(); CP_WAIT(1); }
        else                { CP_WAIT(0); }
        __syncthreads();

        const uint32_t st = sS + (kb & 1) * FS_STAGE;

        // ---- S = Q K^T (16x64 per warp), term-major for accumulator ILP ----
        float s_acc[8][4];
        #pragma unroll
        for (int t = 0; t < 8; t++)
            #pragma unroll
            for (int e = 0; e < 4; e++) s_acc[t][e] = 0.f;

        #pragma unroll
        for (int kt = 0; kt < 8; kt++) {
            uint32_t qaddr = sQ + (w * 16 + ldrow) * FS_STRIDE + kt * 32 + ldoff;
            uint32_t qh_[4], ql_[4];
            ldm_x4(qh_[0], qh_[1], qh_[2], qh_[3], qaddr);
            ldm_x4(ql_[0], ql_[1], ql_[2], ql_[3], qaddr + FS_Q_PLANE);
            uint32_t kh_[4][4], kl_[4][4];
            #pragma unroll
            for (int nt2 = 0; nt2 < 4; nt2++) {
                uint32_t kaddr = st + (nt2 * 16 + ldrow) * FS_STRIDE + kt * 32 + ldoff;
                ldm_x4(kh_[nt2][0], kh_[nt2][1], kh_[nt2][2], kh_[nt2][3], kaddr);
                ldm_x4(kl_[nt2][0], kl_[nt2][1], kl_[nt2][2], kl_[nt2][3],
                       kaddr + FS_KV_PLANE);
            }
            // term 0: qh*kh  (8 independent accs)
            #pragma unroll
            for (int nt2 = 0; nt2 < 4; nt2++)
                #pragma unroll
                for (int sub = 0; sub < 2; sub++) {
                    float* d = s_acc[nt2 * 2 + sub];
                    mma_bf16(d[0], d[1], d[2], d[3],
                             qh_[0], qh_[1], qh_[2], qh_[3],
                             kh_[nt2][sub], kh_[nt2][sub + 2]);
                }
            // term 1: qh*kl
            #pragma unroll
            for (int nt2 = 0; nt2 < 4; nt2++)
                #pragma unroll
                for (int sub = 0; sub < 2; sub++) {
                    float* d = s_acc[nt2 * 2 + sub];
                    mma_bf16(d[0], d[1], d[2], d[3],
                             qh_[0], qh_[1], qh_[2], qh_[3],
                             kl_[nt2][sub], kl_[nt2][sub + 2]);
                }
            // term 2: ql*kh
            #pragma unroll
            for (int nt2 = 0; nt2 < 4; nt2++)
                #pragma unroll
                for (int sub = 0; sub < 2; sub++) {
                    float* d = s_acc[nt2 * 2 + sub];
                    mma_bf16(d[0], d[1], d[2], d[3],
                             ql_[0], ql_[1], ql_[2], ql_[3],
                             kh_[nt2][sub], kh_[nt2][sub + 2]);
                }
        }

        // ---- scale + causal mask ----
        const bool needmask = (kb >= 2 * qb);
        const int colb = kb * 64 + (lane & 3) * 2;
        #pragma unroll
        for (int t = 0; t < 8; t++) {
            #pragma unroll
            for (int e = 0; e < 4; e++) {
                float v = s_acc[t][e] * scale;
                if (needmask) {
                    int col = colb + t * 8 + (e & 1);
                    int row = rlow + ((e >= 2) ? 8 : 0);
                    if (col > row) v = -1e30f;
                }
                s_acc[t][e] = v;
            }
        }

        // ---- online softmax ----
        float rmax0 = -1e30f, rmax1 = -1e30f;
        #pragma unroll
        for (int t = 0; t < 8; t++) {
            rmax0 = fmaxf(rmax0, fmaxf(s_acc[t][0], s_acc[t][1]));
            rmax1 = fmaxf(rmax1, fmaxf(s_acc[t][2], s_acc[t][3]));
        }
        #pragma unroll
        for (int off = 1; off <= 2; off <<= 1) {
            rmax0 = fmaxf(rmax0, __shfl_xor_sync(0xffffffffu, rmax0, off));
            rmax1 = fmaxf(rmax1, __shfl_xor_sync(0xffffffffu, rmax1, off));
        }
        float mn0 = fmaxf(m0, rmax0), mn1 = fmaxf(m1, rmax1);
        float al0 = __expf(m0 - mn0), al1 = __expf(m1 - mn1);
        float sum0 = 0.f, sum1 = 0.f;
        #pragma unroll
        for (int t = 0; t < 8; t++) {
            float p0 = __expf(s_acc[t][0] - mn0);
            float p1 = __expf(s_acc[t][1] - mn0);
            float p2 = __expf(s_acc[t][2] - mn1);
            float p3 = __expf(s_acc[t][3] - mn1);
            s_acc[t][0] = p0; s_acc[t][1] = p1; s_acc[t][2] = p2; s_acc[t][3] = p3;
            sum0 += p0 + p1; sum1 += p2 + p3;
        }
        #pragma unroll
        for (int off = 1; off <= 2; off <<= 1) {
            sum0 += __shfl_xor_sync(0xffffffffu, sum0, off);
            sum1 += __shfl_xor_sync(0xffffffffu, sum1, off);
        }
        l0 = l0 * al0 + sum0;  m0 = mn0;
        l1 = l1 * al1 + sum1;  m1 = mn1;
        #pragma unroll
        for (int t = 0; t < 16; t++) {
            o[t][0] *= al0; o[t][1] *= al0;
            o[t][2] *= al1; o[t][3] *= al1;
        }

        // ---- O += P V, term-major over groups of 4 d-tiles ----
        #pragma unroll
        for (int j = 0; j < 4; j++) {
            float lx[8];
            uint32_t ah[4], alr[4];
            ah[0] = pack_hi(s_acc[2*j][0],   s_acc[2*j][1],   lx[0], lx[1]);
            ah[1] = pack_hi(s_acc[2*j][2],   s_acc[2*j][3],   lx[2], lx[3]);
            ah[2] = pack_hi(s_acc[2*j+1][0], s_acc[2*j+1][1], lx[4], lx[5]);
            ah[3] = pack_hi(s_acc[2*j+1][2], s_acc[2*j+1][3], lx[6], lx[7]);
            alr[0] = pack_bf(lx[0], lx[1]);
            alr[1] = pack_bf(lx[2], lx[3]);
            alr[2] = pack_bf(lx[4], lx[5]);
            alr[3] = pack_bf(lx[6], lx[7]);

            #pragma unroll
            for (int g = 0; g < 2; g++) {
                uint32_t vh4[4][4], vl4[4][4];
                #pragma unroll
                for (int q4 = 0; q4 < 4; q4++) {
                    int dt2 = g * 4 + q4;
                    uint32_t vaddr = st + 2 * FS_KV_PLANE +
                                     (j * 16 + ldrow) * FS_STRIDE + dt2 * 32 + ldoff;
                    ldm_x4_t(vh4[q4][0], vh4[q4][1], vh4[q4][2], vh4[q4][3], vaddr);
                    ldm_x4_t(vl4[q4][0], vl4[q4][1], vl4[q4][2], vl4[q4][3],
                             vaddr + FS_KV_PLANE);
                }
                // term 0: ah * vh  (8 independent accs)
                #pragma unroll
                for (int q4 = 0; q4 < 4; q4++)
                    #pragma unroll
                    for (int sub = 0; sub < 2; sub++) {
                        float* d = o[(g * 4 + q4) * 2 + sub];
                        mma_bf16(d[0], d[1], d[2], d[3],
                                 ah[0], ah[1], ah[2], ah[3],
                                 vh4[q4][2*sub], vh4[q4][2*sub+1]);
                    }
                // term 1: ah * vl
                #pragma unroll
                for (int q4 = 0; q4 < 4; q4++)
                    #pragma unroll
                    for (int sub = 0; sub < 2; sub++) {
                        float* d = o[(g * 4 + q4) * 2 + sub];
                        mma_bf16(d[0], d[1], d[2], d[3],
                                 ah[0], ah[1], ah[2], ah[3],
                                 vl4[q4][2*sub], vl4[q4][2*sub+1]);
                    }
                // term 2: alr * vh
                #pragma unroll
                for (int q4 = 0; q4 < 4; q4++)
                    #pragma unroll
                    for (int sub = 0; sub < 2; sub++) {
                        float* d = o[(g * 4 + q4) * 2 + sub];
                        mma_bf16(d[0], d[1], d[2], d[3],
                                 alr[0], alr[1], alr[2], alr[3],
                                 vh4[q4][2*sub], vh4[q4][2*sub+1]);
                    }
            }
        }
        __syncthreads();
    }

    // ---- normalize + direct bf16 hi/lo store ----
    float inv0 = 1.0f / l0, inv1 = 1.0f / l1;
    const int row0 = q0 + w * 16 + (lane >> 2);
    #pragma unroll
    for (int t = 0; t < 16; t++) {
        int d = t * 8 + (lane & 3) * 2;
        size_t off0 = (size_t)row0 * DMODEL + h * HD + d;
        size_t off1 = off0 + 8 * DMODEL;
        float v0 = o[t][0] * inv0, v1 = o[t][1] * inv0;
        float v2 = o[t][2] * inv1, v3 = o[t][3] * inv1;
        __nv_bfloat16 h0 = __float2bfloat16(v0), h1 = __float2bfloat16(v1);
        __nv_bfloat16 h2 = __float2bfloat16(v2), h3 = __float2bfloat16(v3);
        *(__nv_bfloat162*)&g_Ohi[off0] = __nv_bfloat162(h0, h1);
        *(__nv_bfloat162*)&g_Ohi[off1] = __nv_bfloat162(h2, h3);
        *(__nv_bfloat162*)&g_Olo[off0] = __nv_bfloat162(
            __float2bfloat16(v0 - __bfloat162float(h0)),
            __float2bfloat16(v1 - __bfloat162float(h1)));
        *(__nv_bfloat162*)&g_Olo[off1] = __nv_bfloat162(
            __float2bfloat16(v2 - __bfloat162float(h2)),
            __float2bfloat16(v3 - __bfloat162float(h3)));
    }
}

// ---------------------------------------------------------------------------
extern "C" void kernel_launch(void* const* d_in, const int* in_sizes, int n_in,
                              void* d_out, int out_size)
{
    const float* X    = (const float*)d_in[0];
    const float* cosp = (const float*)d_in[1];
    const float* sinp = (const float*)d_in[2];
    const float* Wq   = (const float*)d_in[3];
    const float* Wk   = (const float*)d_in[4];
    const float* Wv   = (const float*)d_in[5];
    const float* Wo   = (const float*)d_in[6];
    float* out = (float*)d_out;

    float *gQ, *gK, *gV;
    cudaGetSymbolAddress((void**)&gQ, g_Q);
    cudaGetSymbolAddress((void**)&gK, g_K);
    cudaGetSymbolAddress((void**)&gV, g_V);
    __nv_bfloat16 *xh, *xl, *oh, *ol, *qh, *ql, *kh, *kl, *vh, *vl, *wh, *wl;
    __nv_bfloat16 *gvh, *gvl;
    cudaGetSymbolAddress((void**)&xh, g_Xhi);  cudaGetSymbolAddress((void**)&xl, g_Xlo);
    cudaGetSymbolAddress((void**)&oh, g_Ohi);  cudaGetSymbolAddress((void**)&ol, g_Olo);
    cudaGetSymbolAddress((void**)&gvh, g_Vhi); cudaGetSymbolAddress((void**)&gvl, g_Vlo);
    cudaGetSymbolAddress((void**)&qh, g_WqThi); cudaGetSymbolAddress((void**)&ql, g_WqTlo);
    cudaGetSymbolAddress((void**)&kh, g_WkThi); cudaGetSymbolAddress((void**)&kl, g_WkTlo);
    cudaGetSymbolAddress((void**)&vh, g_WvThi); cudaGetSymbolAddress((void**)&vl, g_WvTlo);
    cudaGetSymbolAddress((void**)&wh, g_WoThi); cudaGetSymbolAddress((void**)&wl, g_WoTlo);

    cudaFuncSetAttribute(gemm_mma, cudaFuncAttributeMaxDynamicSharedMemorySize, GEMM_SMEM);
    cudaFuncSetAttribute(flash_mma, cudaFuncAttributeMaxDynamicSharedMemorySize, FLASH_SMEM);

    // splits
    split_rm<<<(S_LEN * DMODEL + 255) / 256, 256>>>(X, xh, xl, S_LEN * DMODEL);
    split_tr<<<dim3(DMODEL / 32, DMODEL / 32), 256>>>(Wq, qh, ql, DMODEL, DMODEL);
    split_tr<<<dim3(KV_DIM / 32, DMODEL / 32), 256>>>(Wk, kh, kl, DMODEL, KV_DIM);
    split_tr<<<dim3(KV_DIM / 32, DMODEL / 32), 256>>>(Wv, vh, vl, DMODEL, KV_DIM);
    split_tr<<<dim3(DMODEL / 32, DMODEL / 32), 256>>>(Wo, wh, wl, DMODEL, DMODEL);

    // QKV projections (tensor core)
    gemm_mma<<<dim3(DMODEL / 128, S_LEN / 128), 256, GEMM_SMEM>>>(
        xh, xl, qh, ql, gQ, S_LEN, DMODEL, DMODEL);
    gemm_mma<<<dim3(KV_DIM / 128, S_LEN / 128), 256, GEMM_SMEM>>>(
        xh, xl, kh, kl, gK, S_LEN, KV_DIM, DMODEL);
    gemm_mma<<<dim3(KV_DIM / 128, S_LEN / 128), 256, GEMM_SMEM>>>(
        xh, xl, vh, vl, gV, S_LEN, KV_DIM, DMODEL);

    // RoPE -> bf16 planes; V -> bf16 planes
    int rthreads = S_LEN * (NH + NKV) * 64;
    rope_split<<<(rthreads + 255) / 256, 256>>>(cosp, sinp);
    split_rm<<<(S_LEN * KV_DIM + 255) / 256, 256>>>(gV, gvh, gvl, S_LEN * KV_DIM);

    // tensor-core flash attention (writes g_Ohi/g_Olo directly)
    flash_mma<<<dim3(S_LEN / 128, NH), 256, FLASH_SMEM>>>();

    // output projection
    gemm_mma<<<dim3(DMODEL / 128, S_LEN / 128), 256, GEMM_SMEM>>>(
        oh, ol, wh, wl, out, S_LEN, DMODEL, DMODEL);
}